// round 5
// baseline (speedup 1.0000x reference)
#include <cuda_runtime.h>
#include <cuda_fp16.h>
#include <cstdint>

// ============================================================
// Typed relational GCN, sm_103 baseline PTX (no tcgen05 allowed).
//   out = sum_k (adj==k) @ (V@w_k) + bias,  N=8192, F=256, fp32.
//
// R5: stage2 retiled. Warp tile M32 x N64 (was M16 x N128):
// same HMMA count, half the B shared-memory traffic (B fragment
// reused across 2 m-tiles). CTA = M256 x N64, grid 32x4.
// ============================================================

#define NROWS 8192
#define FEAT  256
#define NCHUNKS 128                           // K chunks of 64
#define STAGES 4
#define STAGE_BYTES (3 * 8 * 2 * 32 * 16)     // [type][nt][half][lane][16B] = 24576
#define SMEM_TOTAL (STAGES * STAGE_BYTES)     // 98304

// B scratch, fragment-major fp16:
// [type(3)][ntile(32)][kchunk(128)][half(2)][lane(32)][16B] = 12.58 MB
__device__ __align__(256) uint8_t g_B[3u * 32u * 128u * 2u * 32u * 16u];

// ---------------- helpers ---------------------------------------------------

__device__ __forceinline__ uint32_t smem_u32(const void* p) {
    uint32_t a;
    asm("{ .reg .u64 t; cvta.to.shared.u64 t, %1; cvt.u32.u64 %0, t; }" : "=r"(a) : "l"(p));
    return a;
}

// pack low bytes of 4 int32 (values 0..3) into one 4-byte word
__device__ __forceinline__ uint32_t pack4(int a, int b, int c, int d) {
    uint32_t x, y, r;
    asm("prmt.b32 %0, %1, %2, 0x40;"   : "=r"(x) : "r"(a), "r"(b));
    asm("prmt.b32 %0, %1, %2, 0x40;"   : "=r"(y) : "r"(c), "r"(d));
    asm("prmt.b32 %0, %1, %2, 0x5410;" : "=r"(r) : "r"(x), "r"(y));
    return r;
}

__device__ __forceinline__ void mma_f16(float* c,
                                        uint32_t a0, uint32_t a1, uint32_t a2, uint32_t a3,
                                        uint32_t b0, uint32_t b1) {
    asm volatile(
        "mma.sync.aligned.m16n8k16.row.col.f32.f16.f16.f32 "
        "{%0,%1,%2,%3}, {%4,%5,%6,%7}, {%8,%9}, {%0,%1,%2,%3};"
        : "+f"(c[0]), "+f"(c[1]), "+f"(c[2]), "+f"(c[3])
        : "r"(a0), "r"(a1), "r"(a2), "r"(a3), "r"(b0), "r"(b1));
}

__device__ __forceinline__ void cp_async16(uint32_t smem_addr, const void* gptr) {
    asm volatile("cp.async.cg.shared.global [%0], [%1], 16;"
                 :: "r"(smem_addr), "l"(gptr) : "memory");
}
#define CP_COMMIT() asm volatile("cp.async.commit_group;" ::: "memory")
#define CP_WAIT3()  asm volatile("cp.async.wait_group 3;" ::: "memory")
#define CP_WAIT0()  asm volatile("cp.async.wait_group 0;" ::: "memory")

// ---------------- Stage 1: H_k = V @ w_k -> fp16 fragment-major -------------
// grid (128 j-tiles, 4 n-tiles, 3 types), block (16,16). FFMA-roofline bound.

__global__ void stage1_kernel(const float* __restrict__ V,
                              const float* __restrict__ w1,
                              const float* __restrict__ w2,
                              const float* __restrict__ w3) {
    const int j0 = blockIdx.x * 64;
    const int n0 = blockIdx.y * 64;
    const int type = blockIdx.z;
    const float* w = (type == 0) ? w1 : (type == 1) ? w2 : w3;

    __shared__ float Vs[16][68];
    __shared__ float Ws[16][68];
    __shared__ float Ts[64][65];           // [n][j]

    const int tx = threadIdx.x, ty = threadIdx.y;
    const int t = ty * 16 + tx;

    float acc[4][4];
#pragma unroll
    for (int i = 0; i < 4; i++)
#pragma unroll
        for (int j = 0; j < 4; j++) acc[i][j] = 0.f;

    const int vrow = t >> 2, vci = (t & 3) * 4;
    const int wc = t >> 4, wn = (t & 15) * 4;

    for (int ks = 0; ks < 16; ks++) {
        float4 v = *(const float4*)&V[(size_t)(j0 + vrow) * 256 + ks * 16 + vci];
        Vs[vci + 0][vrow] = v.x; Vs[vci + 1][vrow] = v.y;
        Vs[vci + 2][vrow] = v.z; Vs[vci + 3][vrow] = v.w;
        *(float4*)&Ws[wc][wn] = *(const float4*)&w[(size_t)(ks * 16 + wc) * 256 + n0 + wn];
        __syncthreads();
#pragma unroll
        for (int c = 0; c < 16; c++) {
            float4 rv = *(const float4*)&Vs[c][ty * 4];
            float4 rw = *(const float4*)&Ws[c][tx * 4];
            float a[4] = {rv.x, rv.y, rv.z, rv.w};
            float b[4] = {rw.x, rw.y, rw.z, rw.w};
#pragma unroll
            for (int i = 0; i < 4; i++)
#pragma unroll
                for (int j = 0; j < 4; j++) acc[i][j] += a[i] * b[j];
        }
        __syncthreads();
    }
#pragma unroll
    for (int i = 0; i < 4; i++)
#pragma unroll
        for (int j = 0; j < 4; j++) Ts[tx * 4 + j][ty * 4 + i] = acc[i][j];
    __syncthreads();

    // fragment-major fp16 write.
    const int nl = t >> 2;
    const int s = t & 3;
    const int jb = s * 16;
    const int n = n0 + nl;
    const int nt = n >> 3;
    const int kc = blockIdx.x;

#pragma unroll
    for (int c = 0; c < 4; c++) {
        __half2 p01 = __floats2half2_rn(Ts[nl][jb + 2 * c], Ts[nl][jb + 2 * c + 1]);
        __half2 p89 = __floats2half2_rn(Ts[nl][jb + 2 * c + 8], Ts[nl][jb + 2 * c + 9]);
        uint2 val = make_uint2(*reinterpret_cast<uint32_t*>(&p01),
                               *reinterpret_cast<uint32_t*>(&p89));
        const int lane = 4 * (n & 7) + c;
        size_t off = (((((size_t)(type * 32 + nt) * 128 + kc) * 2 + (s >> 1)) * 32 + lane)) * 16
                   + (size_t)(s & 1) * 8;
        *(uint2*)&g_B[off] = val;
    }
}

// ---------------- Stage 2: mask-GEMM, warp tile M32 x N64 -------------------
// grid 128: bid -> (m_tile = bid>>2 of 256 rows, n_q = bid&3 of 64 feats).
// 256 threads, 8 warps. Warp wid owns rows [i0 + wid*32, +32) (two m16 tiles).

__global__ void __launch_bounds__(256, 1)
stage2_kernel(const int* __restrict__ adj,
              const float* __restrict__ bias,
              float* __restrict__ out) {
    extern __shared__ uint8_t smem[];
    const uint32_t smem_base = smem_u32(smem);

    const int tid = threadIdx.x;
    const int wid = tid >> 5, l = tid & 31;
    const int m_tile = blockIdx.x >> 2;
    const int n_q = blockIdx.x & 3;
    const int i0 = m_tile * 256;
    const int n0 = n_q * 64;
    const int li = l & 3;

    // adj row pointers: [mtile m][row pair half ab] -> row i0+wid*32+16m+8ab+(l>>2)
    const int r0 = i0 + wid * 32 + (l >> 2);
    const int2* ap[2][2];
#pragma unroll
    for (int m = 0; m < 2; m++)
#pragma unroll
        for (int ab = 0; ab < 2; ab++)
            ap[m][ab] = (const int2*)(adj + (size_t)(r0 + 16 * m + 8 * ab) * NROWS);

    float acc[2][8][4];
#pragma unroll
    for (int m = 0; m < 2; m++)
#pragma unroll
        for (int nt = 0; nt < 8; nt++)
#pragma unroll
            for (int r = 0; r < 4; r++) acc[m][nt][r] = 0.f;

    // prologue: stage chunks 0..STAGES-2 (1536 x 16B per chunk, 6 per thread)
#pragma unroll
    for (int p = 0; p < STAGES - 1; p++) {
#pragma unroll
        for (int q = 0; q < 6; q++) {
            int idx = tid + 256 * q;                 // 0..1535
            int type = idx >> 9;
            int rem = idx & 511;
            int nt = rem >> 6;
            int hl = (rem >> 5) & 1;
            int lane = rem & 31;
            const uint8_t* src = g_B +
                (((((size_t)(type * 32 + n_q * 8 + nt) * 128 + p) * 2 + hl) * 32 + lane)) * 16;
            cp_async16(smem_base + p * STAGE_BYTES + idx * 16, src);
        }
        CP_COMMIT();
    }

    // preload adj chunk 0: per (m, ab, s): int2 at 8s+li and 8s+li+4
    int2 v[2][2][4][2];
#pragma unroll
    for (int m = 0; m < 2; m++)
#pragma unroll
        for (int ab = 0; ab < 2; ab++)
#pragma unroll
            for (int s = 0; s < 4; s++) {
                v[m][ab][s][0] = ap[m][ab][8 * s + li];
                v[m][ab][s][1] = ap[m][ab][8 * s + li + 4];
            }

    for (int c = 0; c < NCHUNKS; c++) {
        __syncthreads();   // everyone done consuming the buffer being overwritten
        if (c + STAGES - 1 < NCHUNKS) {
            const int p = c + STAGES - 1;
#pragma unroll
            for (int q = 0; q < 6; q++) {
                int idx = tid + 256 * q;
                int type = idx >> 9;
                int rem = idx & 511;
                int nt = rem >> 6;
                int hl = (rem >> 5) & 1;
                int lane = rem & 31;
                const uint8_t* src = g_B +
                    (((((size_t)(type * 32 + n_q * 8 + nt) * 128 + p) * 2 + hl) * 32 + lane)) * 16;
                cp_async16(smem_base + (p & 3) * STAGE_BYTES + idx * 16, src);
            }
        }
        CP_COMMIT();

        // pack current adj bytes: pk[m][ab][s] = [k2li, k2li+1, k2li+8, k2li+9]
        uint32_t pk[2][2][4];
#pragma unroll
        for (int m = 0; m < 2; m++)
#pragma unroll
            for (int ab = 0; ab < 2; ab++)
#pragma unroll
                for (int s = 0; s < 4; s++)
                    pk[m][ab][s] = pack4(v[m][ab][s][0].x, v[m][ab][s][0].y,
                                         v[m][ab][s][1].x, v[m][ab][s][1].y);

        // prefetch adj for next chunk (hidden under this chunk's MMAs)
        if (c + 1 < NCHUNKS) {
            const int base = (c + 1) * 32;
#pragma unroll
            for (int m = 0; m < 2; m++)
#pragma unroll
                for (int ab = 0; ab < 2; ab++)
#pragma unroll
                    for (int s = 0; s < 4; s++) {
                        v[m][ab][s][0] = ap[m][ab][base + 8 * s + li];
                        v[m][ab][s][1] = ap[m][ab][base + 8 * s + li + 4];
                    }
        }

        CP_WAIT3();
        __syncthreads();   // chunk c fully staged & visible

        const uint32_t sb = smem_base + (c & 3) * STAGE_BYTES;
#pragma unroll
        for (int t = 0; t < 3; t++) {
            const uint32_t cmp = 0x01010101u * (t + 1);
            // fp16 one-hot A fragments for both m-tiles, all 4 ksteps
            uint32_t am[2][4][4];
#pragma unroll
            for (int m = 0; m < 2; m++)
#pragma unroll
                for (int s = 0; s < 4; s++) {
                    uint32_t eA = __vcmpeq4(pk[m][0][s], cmp) & 0x01010101u;
                    uint32_t eB = __vcmpeq4(pk[m][1][s], cmp) & 0x01010101u;
                    am[m][s][0] = (eA & 1u) * 0x3C00u + (eA & 0x100u) * 0x3C0000u;
                    am[m][s][1] = (eB & 1u) * 0x3C00u + (eB & 0x100u) * 0x3C0000u;
                    am[m][s][2] = ((eA >> 16) & 1u) * 0x3C00u + ((eA >> 16) & 0x100u) * 0x3C0000u;
                    am[m][s][3] = ((eB >> 16) & 1u) * 0x3C00u + ((eB >> 16) & 0x100u) * 0x3C0000u;
                }
#pragma unroll
            for (int nt = 0; nt < 8; nt++) {
                const uint32_t base = sb + (uint32_t)(((t * 8 + nt) * 2) * 512 + l * 16);
                uint4 u0, u1;
                asm volatile("ld.shared.v4.u32 {%0,%1,%2,%3}, [%4];"
                             : "=r"(u0.x), "=r"(u0.y), "=r"(u0.z), "=r"(u0.w) : "r"(base));
                asm volatile("ld.shared.v4.u32 {%0,%1,%2,%3}, [%4];"
                             : "=r"(u1.x), "=r"(u1.y), "=r"(u1.z), "=r"(u1.w) : "r"(base + 512));
#pragma unroll
                for (int m = 0; m < 2; m++) {
                    mma_f16(acc[m][nt], am[m][0][0], am[m][0][1], am[m][0][2], am[m][0][3], u0.x, u0.y);
                    mma_f16(acc[m][nt], am[m][1][0], am[m][1][1], am[m][1][2], am[m][1][3], u0.z, u0.w);
                    mma_f16(acc[m][nt], am[m][2][0], am[m][2][1], am[m][2][2], am[m][2][3], u1.x, u1.y);
                    mma_f16(acc[m][nt], am[m][3][0], am[m][3][1], am[m][3][2], am[m][3][3], u1.z, u1.w);
                }
            }
        }
    }

    CP_WAIT0();

    // epilogue: out = acc + bias
#pragma unroll
    for (int m = 0; m < 2; m++) {
        const int rowA = r0 + 16 * m;
#pragma unroll
        for (int nt = 0; nt < 8; nt++) {
            int col = n0 + nt * 8 + 2 * (l & 3);
            float b0 = __ldg(&bias[col]);
            float b1 = __ldg(&bias[col + 1]);
            float2 w0 = make_float2(acc[m][nt][0] + b0, acc[m][nt][1] + b1);
            float2 w1 = make_float2(acc[m][nt][2] + b0, acc[m][nt][3] + b1);
            *(float2*)&out[(size_t)rowA * FEAT + col] = w0;
            *(float2*)&out[(size_t)(rowA + 8) * FEAT + col] = w1;
        }
    }
}

// ---------------- launch ---------------------------------------------------

extern "C" void kernel_launch(void* const* d_in, const int* in_sizes, int n_in,
                              void* d_out, int out_size) {
    const float* V    = (const float*)d_in[0];
    const int*   adj  = (const int*)d_in[1];
    const float* w1   = (const float*)d_in[2];
    const float* w2   = (const float*)d_in[3];
    const float* w3   = (const float*)d_in[4];
    const float* bias = (const float*)d_in[5];
    float* out = (float*)d_out;

    cudaFuncSetAttribute(stage2_kernel,
                         cudaFuncAttributeMaxDynamicSharedMemorySize, SMEM_TOTAL);

    stage1_kernel<<<dim3(128, 4, 3), dim3(16, 16)>>>(V, w1, w2, w3);
    stage2_kernel<<<128, 256, SMEM_TOTAL>>>(adj, bias, out);
}

// round 6
// speedup vs baseline: 1.0703x; 1.0703x over previous
#include <cuda_runtime.h>
#include <cuda_fp16.h>
#include <cstdint>

// ============================================================
// Typed relational GCN, sm_103 baseline PTX (no tcgen05 allowed).
//   out = sum_k (adj==k) @ (V@w_k) + bias,  N=8192, F=256, fp32.
//
// R6: warp tile M16 x N64, 2 CTAs/SM (occ 2x), PRMT-based fp16
// one-hot mask construction (ALU /2.5), single barrier per chunk.
// ============================================================

#define NROWS 8192
#define FEAT  256
#define NCHUNKS 128                           // K chunks of 64
#define STAGES 4
#define STAGE_BYTES (3 * 8 * 2 * 32 * 16)     // [type][nt][half][lane][16B] = 24576
#define SMEM_TOTAL (STAGES * STAGE_BYTES)     // 98304 (x2 CTAs = 196608 < 228K)

// B scratch, fragment-major fp16:
// [type(3)][ntile(32)][kchunk(128)][half(2)][lane(32)][16B] = 12.58 MB
__device__ __align__(256) uint8_t g_B[3u * 32u * 128u * 2u * 32u * 16u];

// ---------------- helpers ---------------------------------------------------

__device__ __forceinline__ uint32_t smem_u32(const void* p) {
    uint32_t a;
    asm("{ .reg .u64 t; cvta.to.shared.u64 t, %1; cvt.u32.u64 %0, t; }" : "=r"(a) : "l"(p));
    return a;
}

__device__ __forceinline__ uint32_t prmt(uint32_t a, uint32_t b, uint32_t sel) {
    uint32_t r;
    asm("prmt.b32 %0, %1, %2, %3;" : "=r"(r) : "r"(a), "r"(b), "r"(sel));
    return r;
}

// pack low bytes of 4 int32 (values 0..3) into one 4-byte word
__device__ __forceinline__ uint32_t pack4(int a, int b, int c, int d) {
    uint32_t x, y, r;
    asm("prmt.b32 %0, %1, %2, 0x40;"   : "=r"(x) : "r"(a), "r"(b));
    asm("prmt.b32 %0, %1, %2, 0x40;"   : "=r"(y) : "r"(c), "r"(d));
    asm("prmt.b32 %0, %1, %2, 0x5410;" : "=r"(r) : "r"(x), "r"(y));
    return r;
}

__device__ __forceinline__ void mma_f16(float* c,
                                        uint32_t a0, uint32_t a1, uint32_t a2, uint32_t a3,
                                        uint32_t b0, uint32_t b1) {
    asm volatile(
        "mma.sync.aligned.m16n8k16.row.col.f32.f16.f16.f32 "
        "{%0,%1,%2,%3}, {%4,%5,%6,%7}, {%8,%9}, {%0,%1,%2,%3};"
        : "+f"(c[0]), "+f"(c[1]), "+f"(c[2]), "+f"(c[3])
        : "r"(a0), "r"(a1), "r"(a2), "r"(a3), "r"(b0), "r"(b1));
}

__device__ __forceinline__ void cp_async16(uint32_t smem_addr, const void* gptr) {
    asm volatile("cp.async.cg.shared.global [%0], [%1], 16;"
                 :: "r"(smem_addr), "l"(gptr) : "memory");
}
#define CP_COMMIT() asm volatile("cp.async.commit_group;" ::: "memory")
#define CP_WAIT2()  asm volatile("cp.async.wait_group 2;" ::: "memory")
#define CP_WAIT0()  asm volatile("cp.async.wait_group 0;" ::: "memory")

// ---------------- Stage 1: H_k = V @ w_k -> fp16 fragment-major -------------
// grid (128 j-tiles, 4 n-tiles, 3 types), block (16,16). FFMA-roofline bound.

__global__ void stage1_kernel(const float* __restrict__ V,
                              const float* __restrict__ w1,
                              const float* __restrict__ w2,
                              const float* __restrict__ w3) {
    const int j0 = blockIdx.x * 64;
    const int n0 = blockIdx.y * 64;
    const int type = blockIdx.z;
    const float* w = (type == 0) ? w1 : (type == 1) ? w2 : w3;

    __shared__ float Vs[16][68];
    __shared__ float Ws[16][68];
    __shared__ float Ts[64][65];           // [n][j]

    const int tx = threadIdx.x, ty = threadIdx.y;
    const int t = ty * 16 + tx;

    float acc[4][4];
#pragma unroll
    for (int i = 0; i < 4; i++)
#pragma unroll
        for (int j = 0; j < 4; j++) acc[i][j] = 0.f;

    const int vrow = t >> 2, vci = (t & 3) * 4;
    const int wc = t >> 4, wn = (t & 15) * 4;

    for (int ks = 0; ks < 16; ks++) {
        float4 v = *(const float4*)&V[(size_t)(j0 + vrow) * 256 + ks * 16 + vci];
        Vs[vci + 0][vrow] = v.x; Vs[vci + 1][vrow] = v.y;
        Vs[vci + 2][vrow] = v.z; Vs[vci + 3][vrow] = v.w;
        *(float4*)&Ws[wc][wn] = *(const float4*)&w[(size_t)(ks * 16 + wc) * 256 + n0 + wn];
        __syncthreads();
#pragma unroll
        for (int c = 0; c < 16; c++) {
            float4 rv = *(const float4*)&Vs[c][ty * 4];
            float4 rw = *(const float4*)&Ws[c][tx * 4];
            float a[4] = {rv.x, rv.y, rv.z, rv.w};
            float b[4] = {rw.x, rw.y, rw.z, rw.w};
#pragma unroll
            for (int i = 0; i < 4; i++)
#pragma unroll
                for (int j = 0; j < 4; j++) acc[i][j] += a[i] * b[j];
        }
        __syncthreads();
    }
#pragma unroll
    for (int i = 0; i < 4; i++)
#pragma unroll
        for (int j = 0; j < 4; j++) Ts[tx * 4 + j][ty * 4 + i] = acc[i][j];
    __syncthreads();

    // fragment-major fp16 write.
    const int nl = t >> 2;
    const int s = t & 3;
    const int jb = s * 16;
    const int n = n0 + nl;
    const int nt = n >> 3;
    const int kc = blockIdx.x;

#pragma unroll
    for (int c = 0; c < 4; c++) {
        __half2 p01 = __floats2half2_rn(Ts[nl][jb + 2 * c], Ts[nl][jb + 2 * c + 1]);
        __half2 p89 = __floats2half2_rn(Ts[nl][jb + 2 * c + 8], Ts[nl][jb + 2 * c + 9]);
        uint2 val = make_uint2(*reinterpret_cast<uint32_t*>(&p01),
                               *reinterpret_cast<uint32_t*>(&p89));
        const int lane = 4 * (n & 7) + c;
        size_t off = (((((size_t)(type * 32 + nt) * 128 + kc) * 2 + (s >> 1)) * 32 + lane)) * 16
                   + (size_t)(s & 1) * 8;
        *(uint2*)&g_B[off] = val;
    }
}

// ---------------- Stage 2: mask-GEMM, warp tile M16 x N64, 2 CTAs/SM --------
// grid 256: bid -> (m_tile = bid>>2 of 128 rows, n_q = bid&3 of 64 feats).
// 256 threads, 8 warps. Warp wid owns rows [i0 + wid*16, +16).

__global__ void __launch_bounds__(256, 2)
stage2_kernel(const int* __restrict__ adj,
              const float* __restrict__ bias,
              float* __restrict__ out) {
    extern __shared__ uint8_t smem[];
    const uint32_t smem_base = smem_u32(smem);

    const int tid = threadIdx.x;
    const int wid = tid >> 5, l = tid & 31;
    const int m_tile = blockIdx.x >> 2;
    const int n_q = blockIdx.x & 3;
    const int i0 = m_tile * 128;
    const int n0 = n_q * 64;
    const int li = l & 3;

    const int rowA = i0 + wid * 16 + (l >> 2);
    const int2* aA = (const int2*)(adj + (size_t)rowA * NROWS);
    const int2* aB = (const int2*)(adj + (size_t)(rowA + 8) * NROWS);

    float acc[8][4];
#pragma unroll
    for (int nt = 0; nt < 8; nt++)
#pragma unroll
        for (int r = 0; r < 4; r++) acc[nt][r] = 0.f;

    // prologue: stage chunks 0..2 (1536 x 16B per chunk, 6 per thread)
#pragma unroll
    for (int p = 0; p < STAGES - 1; p++) {
#pragma unroll
        for (int q = 0; q < 6; q++) {
            int idx = tid + 256 * q;                 // 0..1535
            int type = idx >> 9;
            int rem = idx & 511;
            int nt = rem >> 6;
            int hl = (rem >> 5) & 1;
            int lane = rem & 31;
            const uint8_t* src = g_B +
                (((((size_t)(type * 32 + n_q * 8 + nt) * 128 + p) * 2 + hl) * 32 + lane)) * 16;
            cp_async16(smem_base + p * STAGE_BYTES + idx * 16, src);
        }
        CP_COMMIT();
    }

    // preload adj chunk 0: per (ab, s): int2 at 8s+li and 8s+li+4
    int2 v[2][4][2];
#pragma unroll
    for (int s = 0; s < 4; s++) {
        v[0][s][0] = aA[8 * s + li];
        v[0][s][1] = aA[8 * s + li + 4];
        v[1][s][0] = aB[8 * s + li];
        v[1][s][1] = aB[8 * s + li + 4];
    }

    for (int c = 0; c < NCHUNKS; c++) {
        // chunk c staged (last-issued group is c+2 -> wait_group 2 drains c)
        CP_WAIT2();
        __syncthreads();   // c visible to all; all warps done reading c-1

        // issue stage c+3 into buffer (c+3)&3 == (c-1)&3 (now safe)
        if (c + STAGES - 1 < NCHUNKS) {
            const int p = c + STAGES - 1;
#pragma unroll
            for (int q = 0; q < 6; q++) {
                int idx = tid + 256 * q;
                int type = idx >> 9;
                int rem = idx & 511;
                int nt = rem >> 6;
                int hl = (rem >> 5) & 1;
                int lane = rem & 31;
                const uint8_t* src = g_B +
                    (((((size_t)(type * 32 + n_q * 8 + nt) * 128 + p) * 2 + hl) * 32 + lane)) * 16;
                cp_async16(smem_base + (p & 3) * STAGE_BYTES + idx * 16, src);
            }
        }
        CP_COMMIT();

        // pack current adj bytes: pk[ab][s] = [k0, k1, k8, k9] (k0 = 16s+2li)
        uint32_t pk[2][4];
#pragma unroll
        for (int ab = 0; ab < 2; ab++)
#pragma unroll
            for (int s = 0; s < 4; s++)
                pk[ab][s] = pack4(v[ab][s][0].x, v[ab][s][0].y,
                                  v[ab][s][1].x, v[ab][s][1].y);

        // prefetch adj for next chunk (hidden under this chunk's MMAs)
        if (c + 1 < NCHUNKS) {
            const int base = (c + 1) * 32;
#pragma unroll
            for (int s = 0; s < 4; s++) {
                v[0][s][0] = aA[base + 8 * s + li];
                v[0][s][1] = aA[base + 8 * s + li + 4];
                v[1][s][0] = aB[base + 8 * s + li];
                v[1][s][1] = aB[base + 8 * s + li + 4];
            }
        }

        const uint32_t sb = smem_base + (c & 3) * STAGE_BYTES;
#pragma unroll
        for (int t = 0; t < 3; t++) {
            const uint32_t cmp = 0x01010101u * (t + 1);
            // PRMT one-hot fp16 fragments: e bytes 0x3C where adj==t+1,
            // prmt spreads bytes into fp16x2 lanes (0x3C00 = 1.0h).
            uint32_t am[4][4];
#pragma unroll
            for (int s = 0; s < 4; s++) {
                uint32_t eA = __vcmpeq4(pk[0][s], cmp) & 0x3C3C3C3Cu;
                uint32_t eB = __vcmpeq4(pk[1][s], cmp) & 0x3C3C3C3Cu;
                am[s][0] = prmt(eA, 0u, 0x1404u);   // rowA, k = {k0, k1}
                am[s][1] = prmt(eB, 0u, 0x1404u);   // rowB
                am[s][2] = prmt(eA, 0u, 0x3424u);   // rowA, k = {k8, k9}
                am[s][3] = prmt(eB, 0u, 0x3424u);   // rowB
            }
#pragma unroll
            for (int nt = 0; nt < 8; nt++) {
                const uint32_t base = sb + (uint32_t)(((t * 8 + nt) * 2) * 512 + l * 16);
                uint4 u0, u1;
                asm volatile("ld.shared.v4.u32 {%0,%1,%2,%3}, [%4];"
                             : "=r"(u0.x), "=r"(u0.y), "=r"(u0.z), "=r"(u0.w) : "r"(base));
                asm volatile("ld.shared.v4.u32 {%0,%1,%2,%3}, [%4];"
                             : "=r"(u1.x), "=r"(u1.y), "=r"(u1.z), "=r"(u1.w) : "r"(base + 512));
                mma_f16(acc[nt], am[0][0], am[0][1], am[0][2], am[0][3], u0.x, u0.y);
                mma_f16(acc[nt], am[1][0], am[1][1], am[1][2], am[1][3], u0.z, u0.w);
                mma_f16(acc[nt], am[2][0], am[2][1], am[2][2], am[2][3], u1.x, u1.y);
                mma_f16(acc[nt], am[3][0], am[3][1], am[3][2], am[3][3], u1.z, u1.w);
            }
        }
    }

    CP_WAIT0();

    // epilogue: out = acc + bias
#pragma unroll
    for (int nt = 0; nt < 8; nt++) {
        int col = n0 + nt * 8 + 2 * (l & 3);
        float b0 = __ldg(&bias[col]);
        float b1 = __ldg(&bias[col + 1]);
        float2 w0 = make_float2(acc[nt][0] + b0, acc[nt][1] + b1);
        float2 w1 = make_float2(acc[nt][2] + b0, acc[nt][3] + b1);
        *(float2*)&out[(size_t)rowA * FEAT + col] = w0;
        *(float2*)&out[(size_t)(rowA + 8) * FEAT + col] = w1;
    }
}

// ---------------- launch ---------------------------------------------------

extern "C" void kernel_launch(void* const* d_in, const int* in_sizes, int n_in,
                              void* d_out, int out_size) {
    const float* V    = (const float*)d_in[0];
    const int*   adj  = (const int*)d_in[1];
    const float* w1   = (const float*)d_in[2];
    const float* w2   = (const float*)d_in[3];
    const float* w3   = (const float*)d_in[4];
    const float* bias = (const float*)d_in[5];
    float* out = (float*)d_out;

    cudaFuncSetAttribute(stage2_kernel,
                         cudaFuncAttributeMaxDynamicSharedMemorySize, SMEM_TOTAL);

    stage1_kernel<<<dim3(128, 4, 3), dim3(16, 16)>>>(V, w1, w2, w3);
    stage2_kernel<<<256, 256, SMEM_TOTAL>>>(adj, bias, out);
}

// round 7
// speedup vs baseline: 1.0773x; 1.0066x over previous
#include <cuda_runtime.h>
#include <cuda_fp16.h>
#include <cstdint>

// ============================================================
// Typed relational GCN, sm_103 baseline PTX (no tcgen05 allowed).
//   out = sum_k (adj==k) @ (V@w_k) + bias,  N=8192, F=256, fp32.
//
// R7: M32 x N64 warp tile (halved crossbar traffic), PRMT one-hot
// masks, register-cached B fragments with s-outer/nt-inner HMMA
// order (independent consecutive MMAs), single barrier per chunk.
// ============================================================

#define NROWS 8192
#define FEAT  256
#define NCHUNKS 128                           // K chunks of 64
#define STAGES 4
#define STAGE_BYTES (3 * 8 * 2 * 32 * 16)     // [type][nt][half][lane][16B] = 24576
#define SMEM_TOTAL (STAGES * STAGE_BYTES)     // 98304

// B scratch, fragment-major fp16:
// [type(3)][ntile(32)][kchunk(128)][half(2)][lane(32)][16B] = 12.58 MB
__device__ __align__(256) uint8_t g_B[3u * 32u * 128u * 2u * 32u * 16u];

// ---------------- helpers ---------------------------------------------------

__device__ __forceinline__ uint32_t smem_u32(const void* p) {
    uint32_t a;
    asm("{ .reg .u64 t; cvta.to.shared.u64 t, %1; cvt.u32.u64 %0, t; }" : "=r"(a) : "l"(p));
    return a;
}

__device__ __forceinline__ uint32_t prmt(uint32_t a, uint32_t b, uint32_t sel) {
    uint32_t r;
    asm("prmt.b32 %0, %1, %2, %3;" : "=r"(r) : "r"(a), "r"(b), "r"(sel));
    return r;
}

// pack low bytes of 4 int32 (values 0..3) into one 4-byte word
__device__ __forceinline__ uint32_t pack4(int a, int b, int c, int d) {
    uint32_t x, y, r;
    asm("prmt.b32 %0, %1, %2, 0x40;"   : "=r"(x) : "r"(a), "r"(b));
    asm("prmt.b32 %0, %1, %2, 0x40;"   : "=r"(y) : "r"(c), "r"(d));
    asm("prmt.b32 %0, %1, %2, 0x5410;" : "=r"(r) : "r"(x), "r"(y));
    return r;
}

__device__ __forceinline__ void mma_f16(float* c,
                                        uint32_t a0, uint32_t a1, uint32_t a2, uint32_t a3,
                                        uint32_t b0, uint32_t b1) {
    asm volatile(
        "mma.sync.aligned.m16n8k16.row.col.f32.f16.f16.f32 "
        "{%0,%1,%2,%3}, {%4,%5,%6,%7}, {%8,%9}, {%0,%1,%2,%3};"
        : "+f"(c[0]), "+f"(c[1]), "+f"(c[2]), "+f"(c[3])
        : "r"(a0), "r"(a1), "r"(a2), "r"(a3), "r"(b0), "r"(b1));
}

__device__ __forceinline__ void cp_async16(uint32_t smem_addr, const void* gptr) {
    asm volatile("cp.async.cg.shared.global [%0], [%1], 16;"
                 :: "r"(smem_addr), "l"(gptr) : "memory");
}
#define CP_COMMIT() asm volatile("cp.async.commit_group;" ::: "memory")
#define CP_WAIT2()  asm volatile("cp.async.wait_group 2;" ::: "memory")
#define CP_WAIT0()  asm volatile("cp.async.wait_group 0;" ::: "memory")

// ---------------- Stage 1: H_k = V @ w_k -> fp16 fragment-major -------------
// grid (128 j-tiles, 4 n-tiles, 3 types), block (16,16). FFMA-roofline bound.

__global__ void stage1_kernel(const float* __restrict__ V,
                              const float* __restrict__ w1,
                              const float* __restrict__ w2,
                              const float* __restrict__ w3) {
    const int j0 = blockIdx.x * 64;
    const int n0 = blockIdx.y * 64;
    const int type = blockIdx.z;
    const float* w = (type == 0) ? w1 : (type == 1) ? w2 : w3;

    __shared__ float Vs[16][68];
    __shared__ float Ws[16][68];
    __shared__ float Ts[64][65];           // [n][j]

    const int tx = threadIdx.x, ty = threadIdx.y;
    const int t = ty * 16 + tx;

    float acc[4][4];
#pragma unroll
    for (int i = 0; i < 4; i++)
#pragma unroll
        for (int j = 0; j < 4; j++) acc[i][j] = 0.f;

    const int vrow = t >> 2, vci = (t & 3) * 4;
    const int wc = t >> 4, wn = (t & 15) * 4;

    for (int ks = 0; ks < 16; ks++) {
        float4 v = *(const float4*)&V[(size_t)(j0 + vrow) * 256 + ks * 16 + vci];
        Vs[vci + 0][vrow] = v.x; Vs[vci + 1][vrow] = v.y;
        Vs[vci + 2][vrow] = v.z; Vs[vci + 3][vrow] = v.w;
        *(float4*)&Ws[wc][wn] = *(const float4*)&w[(size_t)(ks * 16 + wc) * 256 + n0 + wn];
        __syncthreads();
#pragma unroll
        for (int c = 0; c < 16; c++) {
            float4 rv = *(const float4*)&Vs[c][ty * 4];
            float4 rw = *(const float4*)&Ws[c][tx * 4];
            float a[4] = {rv.x, rv.y, rv.z, rv.w};
            float b[4] = {rw.x, rw.y, rw.z, rw.w};
#pragma unroll
            for (int i = 0; i < 4; i++)
#pragma unroll
                for (int j = 0; j < 4; j++) acc[i][j] += a[i] * b[j];
        }
        __syncthreads();
    }
#pragma unroll
    for (int i = 0; i < 4; i++)
#pragma unroll
        for (int j = 0; j < 4; j++) Ts[tx * 4 + j][ty * 4 + i] = acc[i][j];
    __syncthreads();

    // fragment-major fp16 write.
    const int nl = t >> 2;
    const int s = t & 3;
    const int jb = s * 16;
    const int n = n0 + nl;
    const int nt = n >> 3;
    const int kc = blockIdx.x;

#pragma unroll
    for (int c = 0; c < 4; c++) {
        __half2 p01 = __floats2half2_rn(Ts[nl][jb + 2 * c], Ts[nl][jb + 2 * c + 1]);
        __half2 p89 = __floats2half2_rn(Ts[nl][jb + 2 * c + 8], Ts[nl][jb + 2 * c + 9]);
        uint2 val = make_uint2(*reinterpret_cast<uint32_t*>(&p01),
                               *reinterpret_cast<uint32_t*>(&p89));
        const int lane = 4 * (n & 7) + c;
        size_t off = (((((size_t)(type * 32 + nt) * 128 + kc) * 2 + (s >> 1)) * 32 + lane)) * 16
                   + (size_t)(s & 1) * 8;
        *(uint2*)&g_B[off] = val;
    }
}

// ---------------- Stage 2: mask-GEMM, warp tile M32 x N64 -------------------
// grid 128: bid -> (m_tile = bid>>2 of 256 rows, n_q = bid&3 of 64 feats).
// 256 threads, 8 warps. Warp wid owns rows [i0 + wid*32, +32) (two m16 tiles).

__global__ void __launch_bounds__(256, 1)
stage2_kernel(const int* __restrict__ adj,
              const float* __restrict__ bias,
              float* __restrict__ out) {
    extern __shared__ uint8_t smem[];
    const uint32_t smem_base = smem_u32(smem);

    const int tid = threadIdx.x;
    const int wid = tid >> 5, l = tid & 31;
    const int m_tile = blockIdx.x >> 2;
    const int n_q = blockIdx.x & 3;
    const int i0 = m_tile * 256;
    const int n0 = n_q * 64;
    const int li = l & 3;

    const int r0 = i0 + wid * 32 + (l >> 2);
    const int2* ap[2][2];
#pragma unroll
    for (int m = 0; m < 2; m++)
#pragma unroll
        for (int ab = 0; ab < 2; ab++)
            ap[m][ab] = (const int2*)(adj + (size_t)(r0 + 16 * m + 8 * ab) * NROWS);

    float acc[2][8][4];
#pragma unroll
    for (int m = 0; m < 2; m++)
#pragma unroll
        for (int nt = 0; nt < 8; nt++)
#pragma unroll
            for (int r = 0; r < 4; r++) acc[m][nt][r] = 0.f;

    // prologue: stage chunks 0..2 (1536 x 16B per chunk, 6 per thread)
#pragma unroll
    for (int p = 0; p < STAGES - 1; p++) {
#pragma unroll
        for (int q = 0; q < 6; q++) {
            int idx = tid + 256 * q;                 // 0..1535
            int type = idx >> 9;
            int rem = idx & 511;
            int nt = rem >> 6;
            int hl = (rem >> 5) & 1;
            int lane = rem & 31;
            const uint8_t* src = g_B +
                (((((size_t)(type * 32 + n_q * 8 + nt) * 128 + p) * 2 + hl) * 32 + lane)) * 16;
            cp_async16(smem_base + p * STAGE_BYTES + idx * 16, src);
        }
        CP_COMMIT();
    }

    // adj for chunk 0: load + pack immediately
    uint32_t pk[2][2][4];
#pragma unroll
    for (int m = 0; m < 2; m++)
#pragma unroll
        for (int ab = 0; ab < 2; ab++)
#pragma unroll
            for (int s = 0; s < 4; s++) {
                int2 a0 = ap[m][ab][8 * s + li];
                int2 a1 = ap[m][ab][8 * s + li + 4];
                pk[m][ab][s] = pack4(a0.x, a0.y, a1.x, a1.y);
            }

    for (int c = 0; c < NCHUNKS; c++) {
        // chunk c staged (last-issued group is c+2 -> wait_group 2 drains c)
        CP_WAIT2();
        __syncthreads();   // c visible; all warps done reading buffer (c-1)&3

        // stage chunk c+3 into freed buffer
        if (c + STAGES - 1 < NCHUNKS) {
            const int p = c + STAGES - 1;
#pragma unroll
            for (int q = 0; q < 6; q++) {
                int idx = tid + 256 * q;
                int type = idx >> 9;
                int rem = idx & 511;
                int nt = rem >> 6;
                int hl = (rem >> 5) & 1;
                int lane = rem & 31;
                const uint8_t* src = g_B +
                    (((((size_t)(type * 32 + n_q * 8 + nt) * 128 + p) * 2 + hl) * 32 + lane)) * 16;
                cp_async16(smem_base + (p & 3) * STAGE_BYTES + idx * 16, src);
            }
        }
        CP_COMMIT();

        // issue adj loads for chunk c+1 (consumed at end of this chunk)
        int2 nv[2][2][4][2];
        if (c + 1 < NCHUNKS) {
            const int base = (c + 1) * 32;
#pragma unroll
            for (int m = 0; m < 2; m++)
#pragma unroll
                for (int ab = 0; ab < 2; ab++)
#pragma unroll
                    for (int s = 0; s < 4; s++) {
                        nv[m][ab][s][0] = ap[m][ab][base + 8 * s + li];
                        nv[m][ab][s][1] = ap[m][ab][base + 8 * s + li + 4];
                    }
        }

        const uint32_t sb = smem_base + (c & 3) * STAGE_BYTES;
#pragma unroll
        for (int t = 0; t < 3; t++) {
            // PRMT one-hot fp16 A fragments for both m-tiles, all 4 ksteps
            const uint32_t cmp = 0x01010101u * (t + 1);
            uint32_t am[2][4][4];
#pragma unroll
            for (int m = 0; m < 2; m++)
#pragma unroll
                for (int s = 0; s < 4; s++) {
                    uint32_t eA = __vcmpeq4(pk[m][0][s], cmp) & 0x3C3C3C3Cu;
                    uint32_t eB = __vcmpeq4(pk[m][1][s], cmp) & 0x3C3C3C3Cu;
                    am[m][s][0] = prmt(eA, 0u, 0x1404u);
                    am[m][s][1] = prmt(eB, 0u, 0x1404u);
                    am[m][s][2] = prmt(eA, 0u, 0x3424u);
                    am[m][s][3] = prmt(eB, 0u, 0x3424u);
                }
            // process nt in halves of 4: cache B frags in regs, then issue
            // s-outer / nt-inner so consecutive HMMAs are independent
#pragma unroll
            for (int h = 0; h < 2; h++) {
                uint4 ub[4][2];
#pragma unroll
                for (int n4 = 0; n4 < 4; n4++) {
                    const int ntg = h * 4 + n4;
                    const uint32_t base = sb + (uint32_t)(((t * 8 + ntg) * 2) * 512 + l * 16);
                    asm volatile("ld.shared.v4.u32 {%0,%1,%2,%3}, [%4];"
                                 : "=r"(ub[n4][0].x), "=r"(ub[n4][0].y),
                                   "=r"(ub[n4][0].z), "=r"(ub[n4][0].w) : "r"(base));
                    asm volatile("ld.shared.v4.u32 {%0,%1,%2,%3}, [%4];"
                                 : "=r"(ub[n4][1].x), "=r"(ub[n4][1].y),
                                   "=r"(ub[n4][1].z), "=r"(ub[n4][1].w) : "r"(base + 512));
                }
#pragma unroll
                for (int s = 0; s < 4; s++) {
#pragma unroll
                    for (int n4 = 0; n4 < 4; n4++) {
                        const uint32_t b0 = (s & 1) ? ub[n4][s >> 1].z : ub[n4][s >> 1].x;
                        const uint32_t b1 = (s & 1) ? ub[n4][s >> 1].w : ub[n4][s >> 1].y;
#pragma unroll
                        for (int m = 0; m < 2; m++)
                            mma_f16(acc[m][h * 4 + n4],
                                    am[m][s][0], am[m][s][1], am[m][s][2], am[m][s][3],
                                    b0, b1);
                    }
                }
            }
        }

        // pack next chunk's adj (loads have had the whole MMA phase to land)
        if (c + 1 < NCHUNKS) {
#pragma unroll
            for (int m = 0; m < 2; m++)
#pragma unroll
                for (int ab = 0; ab < 2; ab++)
#pragma unroll
                    for (int s = 0; s < 4; s++)
                        pk[m][ab][s] = pack4(nv[m][ab][s][0].x, nv[m][ab][s][0].y,
                                             nv[m][ab][s][1].x, nv[m][ab][s][1].y);
        }
    }

    CP_WAIT0();

    // epilogue: out = acc + bias
#pragma unroll
    for (int m = 0; m < 2; m++) {
        const int rowA = r0 + 16 * m;
#pragma unroll
        for (int nt = 0; nt < 8; nt++) {
            int col = n0 + nt * 8 + 2 * (l & 3);
            float b0 = __ldg(&bias[col]);
            float b1 = __ldg(&bias[col + 1]);
            float2 w0 = make_float2(acc[m][nt][0] + b0, acc[m][nt][1] + b1);
            float2 w1 = make_float2(acc[m][nt][2] + b0, acc[m][nt][3] + b1);
            *(float2*)&out[(size_t)rowA * FEAT + col] = w0;
            *(float2*)&out[(size_t)(rowA + 8) * FEAT + col] = w1;
        }
    }
}

// ---------------- launch ---------------------------------------------------

extern "C" void kernel_launch(void* const* d_in, const int* in_sizes, int n_in,
                              void* d_out, int out_size) {
    const float* V    = (const float*)d_in[0];
    const int*   adj  = (const int*)d_in[1];
    const float* w1   = (const float*)d_in[2];
    const float* w2   = (const float*)d_in[3];
    const float* w3   = (const float*)d_in[4];
    const float* bias = (const float*)d_in[5];
    float* out = (float*)d_out;

    cudaFuncSetAttribute(stage2_kernel,
                         cudaFuncAttributeMaxDynamicSharedMemorySize, SMEM_TOTAL);

    stage1_kernel<<<dim3(128, 4, 3), dim3(16, 16)>>>(V, w1, w2, w3);
    stage2_kernel<<<128, 256, SMEM_TOTAL>>>(adj, bias, out);
}